// round 12
// baseline (speedup 1.0000x reference)
#include <cuda_runtime.h>

// Shapes: L=4, B=8, C=256, H=W=64
#define LN 4
#define BN 8
#define CN 256
#define HW 4096
#define PBLK 512                 // producers: (lh, c) -> 2 slabs per batch
#define CBLK (BN*CN)             // 2048 consumers: one per (b, c)
#define READY_TARGET (PBLK*2)    // 2 gap publishes per producer block per batch
#define CONS_TARGET  CN          // 256 consumer blocks per batch
#define AHEAD 2                  // producer may lead consumers by 2 batches

__device__ float g_gap[LN*BN*CN];
__device__ int   g_ready[BN];
__device__ int   g_cons[BN];

// Zero flags each call (graph-replay safe).
__global__ void init_kernel() {
    if (threadIdx.x < BN) { g_ready[threadIdx.x] = 0; g_cons[threadIdx.x] = 0; }
}

__device__ __forceinline__ int poll_cg(const int* p) {
    int r;
    asm volatile("ld.global.cg.s32 %0, [%1];" : "=r"(r) : "l"(p));
    return r;
}

__global__ __launch_bounds__(256) void main_kernel(const float* __restrict__ in,
                                                   const float* __restrict__ Wlin,
                                                   float* __restrict__ out) {
    const int bid = blockIdx.x;
    const int tid = threadIdx.x;

    if (bid < PBLK) {
        // ============ PRODUCER: c = bid&255, l in {2*lh, 2*lh+1} ============
        const int c  = bid & 255;
        const int lh = bid >> 8;
        __shared__ float s_warp[2][8];

        for (int b = 0; b < BN; ++b) {
            // Credit throttle: don't run more than AHEAD batches past consumers.
            if (b >= AHEAD) {
                if (tid == 0)
                    while (poll_cg(&g_cons[b - AHEAD]) < CONS_TARGET) __nanosleep(64);
                __syncthreads();
            }

            float acc[2];
#pragma unroll
            for (int sl = 0; sl < 2; ++sl) {
                const int l = 2 * lh + sl;
                const float4* p = reinterpret_cast<const float4*>(in)
                                + (size_t)((l * BN + b) * CN + c) * 1024;
                float a = 0.0f;
#pragma unroll
                for (int k = 0; k < 4; ++k) {
                    float4 v = p[tid + k * 256];      // default: park line in L2
                    a += (v.x + v.y) + (v.z + v.w);
                }
                acc[sl] = a;
            }
#pragma unroll
            for (int off = 16; off; off >>= 1) {
                acc[0] += __shfl_down_sync(0xffffffffu, acc[0], off);
                acc[1] += __shfl_down_sync(0xffffffffu, acc[1], off);
            }
            if ((tid & 31) == 0) {
                s_warp[0][tid >> 5] = acc[0];
                s_warp[1][tid >> 5] = acc[1];
            }
            __syncthreads();
            if (tid < 2) {
                float t = 0.0f;
#pragma unroll
                for (int w = 0; w < 8; ++w) t += s_warp[tid][w];
                const int l = 2 * lh + tid;
                __stcg(&g_gap[(l * BN + b) * CN + c], t * (1.0f / (float)HW));
                __threadfence();                      // release gap before ticket
                atomicAdd(&g_ready[b], 1);
            }
            __syncthreads();
        }
    } else {
        // ================= CONSUMER: q -> (b, c) =================
        const int q = bid - PBLK;
        const int b = q >> 8;
        const int c = q & 255;
        __shared__ float s_sc[LN];

        if (tid == 0)
            while (poll_cg(&g_ready[b]) < READY_TARGET) __nanosleep(64);
        __syncthreads();

        // Scores: warp w computes l=w; lane j covers c' = j*8..j*8+7.
        const int w = tid >> 5, j = tid & 31;
        if (w < LN) {
            const float4* gp = reinterpret_cast<const float4*>(g_gap + (w * BN + b) * CN) + j * 2;
            const float4* wp = reinterpret_cast<const float4*>(Wlin + (size_t)c * CN) + j * 2;
            float4 g0 = gp[0], g1 = gp[1];
            float4 w0 = __ldg(wp), w1 = __ldg(wp + 1);
            float sc = g0.x * w0.x + g0.y * w0.y + g0.z * w0.z + g0.w * w0.w
                     + g1.x * w1.x + g1.y * w1.y + g1.z * w1.z + g1.w * w1.w;
#pragma unroll
            for (int off = 16; off; off >>= 1) sc += __shfl_down_sync(0xffffffffu, sc, off);
            if (j == 0) s_sc[w] = sc;
        }
        __syncthreads();

        float m = fmaxf(fmaxf(s_sc[0], s_sc[1]), fmaxf(s_sc[2], s_sc[3]));
        float e0 = __expf(s_sc[0] - m), e1 = __expf(s_sc[1] - m);
        float e2 = __expf(s_sc[2] - m), e3 = __expf(s_sc[3] - m);
        float inv = 1.0f / ((e0 + e1) + (e2 + e3));
        float attn[LN] = {e0 * inv, e1 * inv, e2 * inv, e3 * inv};

        // Scale 4 slabs: reads are bounded-window L2 hits (producer throttled).
#pragma unroll
        for (int l = 0; l < LN; ++l) {
            const size_t slab = (size_t)((l * BN + b) * CN + c);
            const float4* pi = reinterpret_cast<const float4*>(in) + slab * 1024;
            float4* po = reinterpret_cast<float4*>(out) + slab * 1024;
            const float a = attn[l];
#pragma unroll
            for (int k = 0; k < 4; ++k) {
                float4 v = __ldcs(pi + tid + k * 256);   // dead after read
                v.x *= a; v.y *= a; v.z *= a; v.w *= a;
                __stcs(po + tid + k * 256, v);           // evict-first
            }
        }
        __syncthreads();
        if (tid == 0) atomicAdd(&g_cons[b], 1);          // return credit
    }
}

extern "C" void kernel_launch(void* const* d_in, const int* in_sizes, int n_in,
                              void* d_out, int out_size) {
    const float* in   = (const float*)d_in[0];   // [4,8,256,64,64]
    const float* Wlin = (const float*)d_in[1];   // [256,256]
    float* out = (float*)d_out;

    init_kernel<<<1, 32>>>();
    main_kernel<<<PBLK + CBLK, 256>>>(in, Wlin, out);
}

// round 13
// speedup vs baseline: 1.1357x; 1.1357x over previous
#include <cuda_runtime.h>

// Shapes: L=4, B=8, C=256, H=W=64
#define LN 4
#define BN 8
#define CN 256
#define HW 4096
#define GRIDN 512                // (lhi, c): 2 slabs per block per batch
#define TPB 256
#define LAG 2                    // finish batch b-2 while reading batch b
#define READY_TARGET (GRIDN*2)  // 2 gap publishes per block per batch

__device__ float g_gap[LN*BN*CN];
__device__ int   g_ready[BN];

// Zero flags each call (graph-replay safe).
__global__ void init_kernel() {
    if (threadIdx.x < BN) g_ready[threadIdx.x] = 0;
}

__device__ __forceinline__ int poll_cg(const int* p) {
    int r;
    asm volatile("ld.global.cg.s32 %0, [%1];" : "=r"(r) : "l"(p));
    return r;
}

// Block (lhi=bid>>8, c=bid&255) owns slabs l in {2*lhi, 2*lhi+1} of channel c.
// Iteration b: [A] read batch-b slabs (park in L2), publish gaps;
//              [B] wait flag(b-LAG) (slack -> ~always ready), attn, re-read
//                  batch-(b-LAG) slabs from L2, scale, store.
// Reads(b) and writes(b-2) are concurrently in flight every iteration.
__global__ __launch_bounds__(TPB, 4) void main_kernel(const float* __restrict__ in,
                                                      const float* __restrict__ Wlin,
                                                      float* __restrict__ out) {
    const int bid = blockIdx.x;
    const int c   = bid & 255;
    const int lh  = bid >> 8;
    const int tid = threadIdx.x;
    const int l0  = 2 * lh, l1 = 2 * lh + 1;

    __shared__ float s_warp[2][8];
    __shared__ float s_sc[LN];

    for (int b = 0; b < BN + LAG; ++b) {
        float4 va[4], vb[4];

        // ---- [A1] issue batch-b reads (in flight through any flag spin) ----
        if (b < BN) {
            const float4* p0 = reinterpret_cast<const float4*>(in)
                             + (size_t)((l0 * BN + b) * CN + c) * 1024;
            const float4* p1 = reinterpret_cast<const float4*>(in)
                             + (size_t)((l1 * BN + b) * CN + c) * 1024;
#pragma unroll
            for (int k = 0; k < 4; ++k) {
                va[k] = __ldg(p0 + tid + k * 256);   // default: park line in L2
                vb[k] = __ldg(p1 + tid + k * 256);
            }
        }

        // ---- [B] finish batch b-LAG ----
        if (b >= LAG) {
            const int bb = b - LAG;
            if (tid == 0)
                while (poll_cg(&g_ready[bb]) < READY_TARGET) __nanosleep(64);
            __syncthreads();

            // Scores: warp w -> level w; lane j covers c' = j*8..j*8+7.
            const int w = tid >> 5, j = tid & 31;
            if (w < LN) {
                const float4* gp = reinterpret_cast<const float4*>(g_gap + (w * BN + bb) * CN) + j * 2;
                const float4* wp = reinterpret_cast<const float4*>(Wlin + (size_t)c * CN) + j * 2;
                float4 g0 = gp[0], g1 = gp[1];
                float4 w0 = __ldg(wp), w1 = __ldg(wp + 1);
                float sc = g0.x * w0.x + g0.y * w0.y + g0.z * w0.z + g0.w * w0.w
                         + g1.x * w1.x + g1.y * w1.y + g1.z * w1.z + g1.w * w1.w;
#pragma unroll
                for (int off = 16; off; off >>= 1)
                    sc += __shfl_down_sync(0xffffffffu, sc, off);
                if (j == 0) s_sc[w] = sc;
            }
            __syncthreads();

            float m  = fmaxf(fmaxf(s_sc[0], s_sc[1]), fmaxf(s_sc[2], s_sc[3]));
            float e0 = __expf(s_sc[0] - m), e1 = __expf(s_sc[1] - m);
            float e2 = __expf(s_sc[2] - m), e3 = __expf(s_sc[3] - m);
            float inv = 1.0f / ((e0 + e1) + (e2 + e3));
            const float a0 = (l0 == 0 ? e0 : l0 == 1 ? e1 : l0 == 2 ? e2 : e3) * inv;
            const float a1 = (l1 == 0 ? e0 : l1 == 1 ? e1 : l1 == 2 ? e2 : e3) * inv;

            // Re-read batch-bb slabs (L2 hits: parked 2 iterations ago), store.
#pragma unroll
            for (int sl = 0; sl < 2; ++sl) {
                const int l = l0 + sl;
                const float a = sl ? a1 : a0;
                const size_t slab = (size_t)((l * BN + bb) * CN + c);
                const float4* pi = reinterpret_cast<const float4*>(in)  + slab * 1024;
                float4*       po = reinterpret_cast<float4*>(out)       + slab * 1024;
#pragma unroll
                for (int k = 0; k < 4; ++k) {
                    float4 v = __ldcs(pi + tid + k * 256);   // dead after read
                    v.x *= a; v.y *= a; v.z *= a; v.w *= a;
                    __stcs(po + tid + k * 256, v);           // evict-first
                }
            }
            __syncthreads();   // s_sc reused next iteration
        }

        // ---- [A2] reduce batch-b sums, publish gaps + ready ----
        if (b < BN) {
            float acc0 = 0.0f, acc1 = 0.0f;
#pragma unroll
            for (int k = 0; k < 4; ++k) {
                acc0 += (va[k].x + va[k].y) + (va[k].z + va[k].w);
                acc1 += (vb[k].x + vb[k].y) + (vb[k].z + vb[k].w);
            }
#pragma unroll
            for (int off = 16; off; off >>= 1) {
                acc0 += __shfl_down_sync(0xffffffffu, acc0, off);
                acc1 += __shfl_down_sync(0xffffffffu, acc1, off);
            }
            if ((tid & 31) == 0) {
                s_warp[0][tid >> 5] = acc0;
                s_warp[1][tid >> 5] = acc1;
            }
            __syncthreads();
            if (tid < 2) {
                float t = 0.0f;
#pragma unroll
                for (int w = 0; w < 8; ++w) t += s_warp[tid][w];
                const int l = l0 + tid;
                __stcg(&g_gap[(l * BN + b) * CN + c], t * (1.0f / (float)HW));
                __threadfence();                  // release gap before ticket
                atomicAdd(&g_ready[b], 1);
            }
            __syncthreads();   // s_warp reused next iteration
        }
    }
}

extern "C" void kernel_launch(void* const* d_in, const int* in_sizes, int n_in,
                              void* d_out, int out_size) {
    const float* in   = (const float*)d_in[0];   // [4,8,256,64,64]
    const float* Wlin = (const float*)d_in[1];   // [256,256]
    float* out = (float*)d_out;

    init_kernel<<<1, 32>>>();
    main_kernel<<<GRIDN, TPB>>>(in, Wlin, out);
}

// round 14
// speedup vs baseline: 1.2431x; 1.0946x over previous
#include <cuda_runtime.h>

// Shapes: L=4, B=8, C=256, H=W=64
#define LN 4
#define BN 8
#define CN 256
#define HW 4096
#define GRIDN (LN*CN)            // 1024 blocks: one slab (l, c) per batch
#define TPB 256
#define LAG 2                    // finish batch b-2 while reading batch b
#define READY_TARGET GRIDN       // 1 gap publish per block per batch

__device__ float g_gap[LN*BN*CN];
__device__ int   g_ready[BN];

// Zero flags each call (graph-replay safe).
__global__ void init_kernel() {
    if (threadIdx.x < BN) g_ready[threadIdx.x] = 0;
}

__device__ __forceinline__ int poll_cg(const int* p) {
    int r;
    asm volatile("ld.global.cg.s32 %0, [%1];" : "=r"(r) : "l"(p));
    return r;
}

// Block (l = bid>>8, c = bid&255) owns slab (l, b, c) for every batch b.
// Iteration b: [A] stream-read batch-b slab (parks lines in L2), reduce,
//                  publish gap + ticket;
//              [B] finish batch b-LAG: wait ticket (usually already set),
//                  scores + softmax, re-read slab from L2, scale, store.
// No long-lived register payload -> <=32 regs -> 8 blocks/SM -> 64 warps/SM,
// double R13's warp pool => ~2x outstanding loads (the latency-bound fix).
// 1184 resident slots >= 1024 blocks: flag waits are deadlock-free.
__global__ __launch_bounds__(TPB, 8) void main_kernel(const float* __restrict__ in,
                                                      const float* __restrict__ Wlin,
                                                      float* __restrict__ out) {
    const int bid = blockIdx.x;
    const int c   = bid & 255;
    const int l   = bid >> 8;
    const int tid = threadIdx.x;

    __shared__ float s_warp[8];
    __shared__ float s_sc[LN];

    for (int b = 0; b < BN + LAG; ++b) {
        // ---- [A] read + reduce batch-b slab, publish ----
        if (b < BN) {
            const float4* p = reinterpret_cast<const float4*>(in)
                            + (size_t)((l * BN + b) * CN + c) * 1024;
            float acc = 0.0f;
#pragma unroll
            for (int k = 0; k < 4; ++k) {
                float4 v = __ldg(p + tid + k * 256);   // default: park line in L2
                acc += (v.x + v.y) + (v.z + v.w);
            }
#pragma unroll
            for (int off = 16; off; off >>= 1)
                acc += __shfl_down_sync(0xffffffffu, acc, off);
            if ((tid & 31) == 0) s_warp[tid >> 5] = acc;
            __syncthreads();
            if (tid == 0) {
                float t = 0.0f;
#pragma unroll
                for (int w = 0; w < 8; ++w) t += s_warp[w];
                __stcg(&g_gap[(l * BN + b) * CN + c], t * (1.0f / (float)HW));
                __threadfence();                       // release gap before ticket
                atomicAdd(&g_ready[b], 1);
            }
            // no syncthreads needed here: s_warp not reused until next iter's
            // sync below; but next iteration's [A] writes s_warp -> guard at end.
        }

        // ---- [B] finish batch b-LAG ----
        if (b >= LAG) {
            const int bb = b - LAG;
            if (tid == 0)
                while (poll_cg(&g_ready[bb]) < READY_TARGET) __nanosleep(64);
            __syncthreads();

            // Scores: warp w -> level w; lane j covers c' = j*8..j*8+7.
            const int w = tid >> 5, j = tid & 31;
            if (w < LN) {
                const float4* gp = reinterpret_cast<const float4*>(g_gap + (w * BN + bb) * CN) + j * 2;
                const float4* wp = reinterpret_cast<const float4*>(Wlin + (size_t)c * CN) + j * 2;
                float4 g0 = gp[0], g1 = gp[1];
                float4 w0 = __ldg(wp), w1 = __ldg(wp + 1);
                float sc = g0.x * w0.x + g0.y * w0.y + g0.z * w0.z + g0.w * w0.w
                         + g1.x * w1.x + g1.y * w1.y + g1.z * w1.z + g1.w * w1.w;
#pragma unroll
                for (int off = 16; off; off >>= 1)
                    sc += __shfl_down_sync(0xffffffffu, sc, off);
                if (j == 0) s_sc[w] = sc;
            }
            __syncthreads();

            float m  = fmaxf(fmaxf(s_sc[0], s_sc[1]), fmaxf(s_sc[2], s_sc[3]));
            float e0 = __expf(s_sc[0] - m), e1 = __expf(s_sc[1] - m);
            float e2 = __expf(s_sc[2] - m), e3 = __expf(s_sc[3] - m);
            float inv = 1.0f / ((e0 + e1) + (e2 + e3));
            const float a = (l == 0 ? e0 : l == 1 ? e1 : l == 2 ? e2 : e3) * inv;

            // Re-read batch-bb slab (parked in L2 two iterations ago), store.
            const size_t slab = (size_t)((l * BN + bb) * CN + c);
            const float4* pi = reinterpret_cast<const float4*>(in)  + slab * 1024;
            float4*       po = reinterpret_cast<float4*>(out)       + slab * 1024;
#pragma unroll
            for (int k = 0; k < 4; ++k) {
                float4 v = __ldcs(pi + tid + k * 256);   // dead after read
                v.x *= a; v.y *= a; v.z *= a; v.w *= a;
                __stcs(po + tid + k * 256, v);           // evict-first
            }
        }
        __syncthreads();   // protect s_warp / s_sc across iterations
    }
}

extern "C" void kernel_launch(void* const* d_in, const int* in_sizes, int n_in,
                              void* d_out, int out_size) {
    const float* in   = (const float*)d_in[0];   // [4,8,256,64,64]
    const float* Wlin = (const float*)d_in[1];   // [256,256]
    float* out = (float*)d_out;

    init_kernel<<<1, 32>>>();
    main_kernel<<<GRIDN, TPB>>>(in, Wlin, out);
}